// round 15
// baseline (speedup 1.0000x reference)
#include <cuda_runtime.h>
#include <cuda_bf16.h>
#include <cstdint>

// ---------------- problem constants ----------------
#define SEQ    512
#define BATCH  64
#define IN_W   256
#define SW     1024
#define OUT_W  256

// ---------------- kernel config --------------------
#define P_CTAS   128     // 2 row-halves x 64 col-groups
#define DOM_CTAS 64      // arrivals per barrier domain (one half)
#define NTHREADS 256     // 8 warps = 2 n-halves x 4 k-quarters
#define JS       16      // output columns per CTA
#define RWS      32      // batch rows per CTA
#define STR      16      // subtile rows
#define PADC     1032    // padded row stride, K=1024 bufs (2064B = 16 mod 128)
#define PADX     264     // padded row stride, K=256 bufs (528B = 16 mod 128)

#define LIN_F 0.99999f
__device__ __constant__ float EPS_F = (float)(1.0 - 0.99999);

// ---------------- smem byte offsets (total 196608 = 192KB) ----------------
#define W1PP_OFF 0
#define M_OFF    33024
#define W2_OFF   66048
#define XW_OFF   99072
#define ACT0_OFF 107520
#define ACT1_OFF 140544
#define XACT_OFF 173568
#define RED_OFF  190464
#define SMEM_TOTAL 196608

// ---------------- global scratch ----------------
__device__ float          d_Uf[2][BATCH * SW];   // fp32 u_t (ping-pong)
__device__ __nv_bfloat16  d_Uh[2][BATCH * SW];   // bf16 u_t
__device__ __nv_bfloat16  d_Hh[2][BATCH * SW];   // bf16 h_t (ping-pong)
__device__ float          d_M[SW * SW];          // M = W1p @ W2  (fp32, 4MB)
__device__ float          d_c2[SW];              // c2[j] = W1p[j,:]·b2
__device__ int            d_inv[SW];             // inverse permutation
__device__ unsigned       d_cnt[2 * 8 * 64];     // 2 domains x 8 distributed counters

// ---------------- helpers ----------------
static __device__ __forceinline__ unsigned smem_u32(const void* p) {
    return (unsigned)__cvta_generic_to_shared(p);
}

static __device__ __forceinline__ void bar_arrive(int dom, int cg) {
    __syncthreads();
    if (threadIdx.x == 0) {
        unsigned* cnt = d_cnt + dom * 8 * 64 + (cg & 7) * 64;
        asm volatile("red.release.gpu.global.add.u32 [%0], 1;" :: "l"(cnt) : "memory");
    }
}
// MLP-friendly poll: 8 independent relaxed loads per round, acquire fence on exit
static __device__ __forceinline__ void bar_wait(int dom, unsigned target) {
    if (threadIdx.x == 0) {
        unsigned* base = d_cnt + dom * 8 * 64;
        while (true) {
            unsigned v0, v1, v2, v3, v4, v5, v6, v7;
            asm volatile("ld.relaxed.gpu.u32 %0, [%1];" : "=r"(v0) : "l"(base + 0 * 64) : "memory");
            asm volatile("ld.relaxed.gpu.u32 %0, [%1];" : "=r"(v1) : "l"(base + 1 * 64) : "memory");
            asm volatile("ld.relaxed.gpu.u32 %0, [%1];" : "=r"(v2) : "l"(base + 2 * 64) : "memory");
            asm volatile("ld.relaxed.gpu.u32 %0, [%1];" : "=r"(v3) : "l"(base + 3 * 64) : "memory");
            asm volatile("ld.relaxed.gpu.u32 %0, [%1];" : "=r"(v4) : "l"(base + 4 * 64) : "memory");
            asm volatile("ld.relaxed.gpu.u32 %0, [%1];" : "=r"(v5) : "l"(base + 5 * 64) : "memory");
            asm volatile("ld.relaxed.gpu.u32 %0, [%1];" : "=r"(v6) : "l"(base + 6 * 64) : "memory");
            asm volatile("ld.relaxed.gpu.u32 %0, [%1];" : "=r"(v7) : "l"(base + 7 * 64) : "memory");
            unsigned total = v0 + v1 + v2 + v3 + v4 + v5 + v6 + v7;
            if (total >= target) break;
        }
        asm volatile("fence.acq_rel.gpu;" ::: "memory");
    }
    __syncthreads();
}

static __device__ __forceinline__ void ldsm4(uint32_t& r0, uint32_t& r1, uint32_t& r2, uint32_t& r3,
                                             unsigned addr) {
    asm volatile("ldmatrix.sync.aligned.m8n8.x4.shared.b16 {%0,%1,%2,%3}, [%4];"
                 : "=r"(r0), "=r"(r1), "=r"(r2), "=r"(r3) : "r"(addr));
}
static __device__ __forceinline__ void mma16816(float* c,
                                                uint32_t a0, uint32_t a1, uint32_t a2, uint32_t a3,
                                                uint32_t b0, uint32_t b1) {
    asm("mma.sync.aligned.m16n8k16.row.col.f32.bf16.bf16.f32 "
        "{%0,%1,%2,%3}, {%4,%5,%6,%7}, {%8,%9}, {%0,%1,%2,%3};\n"
        : "+f"(c[0]), "+f"(c[1]), "+f"(c[2]), "+f"(c[3])
        : "r"(a0), "r"(a1), "r"(a2), "r"(a3), "r"(b0), "r"(b1));
}
static __device__ __forceinline__ void ld2cg(float& a, float& b, const float* p) {
    asm volatile("ld.global.cg.v2.f32 {%0,%1}, [%2];" : "=f"(a), "=f"(b) : "l"(p));
}
static __device__ __forceinline__ float ldcg_f(const float* p) {
    float v;
    asm volatile("ld.global.cg.f32 %0, [%1];" : "=f"(v) : "l"(p));
    return v;
}
static __device__ __forceinline__ void st2cg(float* p, float a, float b) {
    asm volatile("st.global.cg.v2.f32 [%0], {%1,%2};" :: "l"(p), "f"(a), "f"(b));
}

// K=1024 GEMM (per-warp K=256), dual accumulators
static __device__ __forceinline__ void gemmK1024(unsigned aA, unsigned aB, int nhalf, float* acc) {
    float acc2[4] = {0.f, 0.f, 0.f, 0.f};
#pragma unroll
    for (int ki = 0; ki < 16; ki += 2) {
        uint32_t a0,a1,a2,a3,b0,b1,b2,b3;
        ldsm4(a0,a1,a2,a3, aA + ki*32);
        ldsm4(b0,b1,b2,b3, aB + ki*32);
        if (nhalf == 0) mma16816(acc, a0,a1,a2,a3, b0,b2);
        else            mma16816(acc, a0,a1,a2,a3, b1,b3);
        ldsm4(a0,a1,a2,a3, aA + (ki+1)*32);
        ldsm4(b0,b1,b2,b3, aB + (ki+1)*32);
        if (nhalf == 0) mma16816(acc2, a0,a1,a2,a3, b0,b2);
        else            mma16816(acc2, a0,a1,a2,a3, b1,b3);
    }
#pragma unroll
    for (int u = 0; u < 4; u++) acc[u] += acc2[u];
}

// K=1024 GEMM with shared A and two B matrices (M', W2), DUAL accumulators each
static __device__ __forceinline__ void gemmK1024x2(unsigned aA, unsigned bM, unsigned bW,
                                                   int nhalf, float* zy, float* yy) {
    float zy2[4] = {0.f, 0.f, 0.f, 0.f};
    float yy2[4] = {0.f, 0.f, 0.f, 0.f};
#pragma unroll
    for (int ki = 0; ki < 16; ki += 2) {
        uint32_t a0,a1,a2,a3, m0,m1,m2,m3, w0,w1,w2,w3;
        ldsm4(a0,a1,a2,a3, aA + ki*32);
        ldsm4(m0,m1,m2,m3, bM + ki*32);
        ldsm4(w0,w1,w2,w3, bW + ki*32);
        if (nhalf == 0) { mma16816(zy, a0,a1,a2,a3, m0,m2); mma16816(yy, a0,a1,a2,a3, w0,w2); }
        else            { mma16816(zy, a0,a1,a2,a3, m1,m3); mma16816(yy, a0,a1,a2,a3, w1,w3); }
        ldsm4(a0,a1,a2,a3, aA + (ki+1)*32);
        ldsm4(m0,m1,m2,m3, bM + (ki+1)*32);
        ldsm4(w0,w1,w2,w3, bW + (ki+1)*32);
        if (nhalf == 0) { mma16816(zy2, a0,a1,a2,a3, m0,m2); mma16816(yy2, a0,a1,a2,a3, w0,w2); }
        else            { mma16816(zy2, a0,a1,a2,a3, m1,m3); mma16816(yy2, a0,a1,a2,a3, w1,w3); }
    }
#pragma unroll
    for (int u = 0; u < 4; u++) { zy[u] += zy2[u]; yy[u] += yy2[u]; }
}

// K=256 GEMM (x-term), accumulate into zy
static __device__ __forceinline__ void gemmK256(unsigned aA, unsigned aB, int nhalf, float* zy) {
#pragma unroll
    for (int ki = 0; ki < 4; ki++) {
        uint32_t a0,a1,a2,a3,b0,b1,b2,b3;
        ldsm4(a0,a1,a2,a3, aA + ki*32);
        ldsm4(b0,b1,b2,b3, aB + ki*32);
        if (nhalf == 0) mma16816(zy, a0,a1,a2,a3, b0,b2);
        else            mma16816(zy, a0,a1,a2,a3, b1,b3);
    }
}

// 4-way k-reduction of (z[4], y[4])
static __device__ __forceinline__ void kreduce8(float* Red, int nhalf, int kq, int lane,
                                                float* z, float* y) {
    if (kq > 0) {
        float* s = Red + ((kq - 1) * 2 + nhalf) * 256;
#pragma unroll
        for (int u = 0; u < 4; u++) { s[u*32 + lane] = z[u]; s[(u+4)*32 + lane] = y[u]; }
    }
    __syncthreads();
    if (kq == 0) {
#pragma unroll
        for (int k = 0; k < 3; k++) {
            const float* s = Red + (k * 2 + nhalf) * 256;
#pragma unroll
            for (int u = 0; u < 4; u++) { z[u] += s[u*32 + lane]; y[u] += s[(u+4)*32 + lane]; }
        }
    }
}

// ---------------- setup 0: inv, u0, counters ----------------
__global__ void setup0(const float* __restrict__ x, const float* __restrict__ init,
                       const int* __restrict__ rp) {
    int tid = blockIdx.x * blockDim.x + threadIdx.x;
    if (tid < 2 * 8 * 64) d_cnt[tid] = 0u;
    if (tid < SW) d_inv[rp[tid]] = tid;
    const float eps = EPS_F;
    for (int e = tid; e < BATCH * SW; e += gridDim.x * blockDim.x) {
        int b = e >> 10, p = e & (SW - 1);
        float v = eps * init[p];
        if (p < IN_W) v += x[b * IN_W + p];
        d_Uf[0][b * SW + p] = v;
        d_Uh[0][b * SW + p] = __float2bfloat16(v);
    }
}

// ---------------- fused setup: M (blocks 0-1023), h0 (1024-1087), c2 (1088-1215) ----
__global__ void setup_rest(const float* __restrict__ W1, const float* __restrict__ b1,
                           const float* __restrict__ W2, const float* __restrict__ b2,
                           const int* __restrict__ rp) {
    __shared__ float As[32][33], Bs[32][33];
    const int bid = blockIdx.x;
    const int tx = threadIdx.x & 15, ty = threadIdx.x >> 4;
    const int lin = threadIdx.x;

    if (bid < 1024) {
        // ---- M[j,m] = sum_i W1[j,i] * W2[rp[i], m] ----
        int jb = (bid >> 5) * 32, mb = (bid & 31) * 32;
        float acc00 = 0.f, acc01 = 0.f, acc10 = 0.f, acc11 = 0.f;
        for (int kc = 0; kc < 32; kc++) {
#pragma unroll
            for (int i = 0; i < 4; i++) {
                int e = lin + i * 256;
                int r = e >> 5, c = e & 31;
                As[r][c] = W1[(size_t)(jb + r) * SW + kc * 32 + c];
                Bs[r][c] = W2[(size_t)rp[kc * 32 + r] * SW + mb + c];
            }
            __syncthreads();
#pragma unroll
            for (int kk = 0; kk < 32; kk++) {
                float a0 = As[ty * 2][kk], a1 = As[ty * 2 + 1][kk];
                float b0 = Bs[kk][tx * 2], b1 = Bs[kk][tx * 2 + 1];
                acc00 += a0 * b0; acc01 += a0 * b1;
                acc10 += a1 * b0; acc11 += a1 * b1;
            }
            __syncthreads();
        }
        d_M[(size_t)(jb + ty * 2)     * SW + mb + tx * 2]     = acc00;
        d_M[(size_t)(jb + ty * 2)     * SW + mb + tx * 2 + 1] = acc01;
        d_M[(size_t)(jb + ty * 2 + 1) * SW + mb + tx * 2]     = acc10;
        d_M[(size_t)(jb + ty * 2 + 1) * SW + mb + tx * 2 + 1] = acc11;
    } else if (bid < 1088) {
        // ---- h0[b,j] = relu(sum_k u0[b,rp[k]] * W1[j,k] + b1[j]) ----
        int lb = bid - 1024;
        int bb = (lb >> 5) * 32, jb = (lb & 31) * 32;
        float acc00 = 0.f, acc01 = 0.f, acc10 = 0.f, acc11 = 0.f;
        for (int kc = 0; kc < 32; kc++) {
#pragma unroll
            for (int i = 0; i < 4; i++) {
                int e = lin + i * 256;
                int r = e >> 5, c = e & 31;
                As[r][c] = d_Uf[0][(size_t)(bb + r) * SW + rp[kc * 32 + c]];
                Bs[r][c] = W1[(size_t)(jb + r) * SW + kc * 32 + c];
            }
            __syncthreads();
#pragma unroll
            for (int kk = 0; kk < 32; kk++) {
                float a0 = As[ty * 2][kk], a1 = As[ty * 2 + 1][kk];
                float b0 = Bs[tx * 2][kk], b1 = Bs[tx * 2 + 1][kk];
                acc00 += a0 * b0; acc01 += a0 * b1;
                acc10 += a1 * b0; acc11 += a1 * b1;
            }
            __syncthreads();
        }
        int j0 = jb + tx * 2, j1 = j0 + 1;
        d_Hh[0][(size_t)(bb + ty*2)     * SW + j0] = __float2bfloat16(fmaxf(acc00 + b1[j0], 0.f));
        d_Hh[0][(size_t)(bb + ty*2)     * SW + j1] = __float2bfloat16(fmaxf(acc01 + b1[j1], 0.f));
        d_Hh[0][(size_t)(bb + ty*2 + 1) * SW + j0] = __float2bfloat16(fmaxf(acc10 + b1[j0], 0.f));
        d_Hh[0][(size_t)(bb + ty*2 + 1) * SW + j1] = __float2bfloat16(fmaxf(acc11 + b1[j1], 0.f));
    } else {
        // ---- c2[j] = sum_i W1[j,i]*b2[rp[i]] ----
        float* pb2 = &As[0][0];
        for (int k = lin; k < SW; k += 256) pb2[k] = b2[rp[k]];
        __syncthreads();
        int warp = lin >> 5, lane = lin & 31;
        int j = (bid - 1088) * 8 + warp;
        float acc = 0.f;
        for (int i = lane; i < SW; i += 32) acc += W1[(size_t)j * SW + i] * pb2[i];
#pragma unroll
        for (int o = 16; o > 0; o >>= 1) acc += __shfl_down_sync(0xffffffff, acc, o);
        if (lane == 0) d_c2[j] = acc;
    }
}

// ---------------- persistent one-barrier-per-step RNN kernel ----------------
__global__ void __launch_bounds__(NTHREADS)
resrnn_kernel(const float* __restrict__ x, const int* __restrict__ rp,
              const float* __restrict__ W1, const float* __restrict__ b1,
              const float* __restrict__ W2, const float* __restrict__ b2,
              float* __restrict__ out, int out_size) {
    extern __shared__ char smem[];
    __nv_bfloat16* W1pps = (__nv_bfloat16*)(smem + W1PP_OFF);  // [16][PADC]  lin·W1pp
    __nv_bfloat16* Ms    = (__nv_bfloat16*)(smem + M_OFF);     // [16][PADC]  eps·M
    __nv_bfloat16* W2s   = (__nv_bfloat16*)(smem + W2_OFF);    // [16][PADC]
    __nv_bfloat16* Xws   = (__nv_bfloat16*)(smem + XW_OFF);    // [16][PADX]  W1p (plain)
    __nv_bfloat16* Act0  = (__nv_bfloat16*)(smem + ACT0_OFF);  // [16][PADC] (u subtile)
    __nv_bfloat16* Act1  = (__nv_bfloat16*)(smem + ACT1_OFF);  // [16][PADC] (h subtile)
    char*          XactB = smem + XACT_OFF;                     // [32][PADX] bf16
    float*         Red   = (float*)(smem + RED_OFF);            // [6][256]

    const int tid   = threadIdx.x;
    const int cta   = blockIdx.x;
    const int cg    = cta & 63;
    const int bh    = cta >> 6;                 // row half = barrier domain
    const int jbase = cg * JS;
    const int rbase = bh * RWS;
    const float eps = EPS_F;

    // ---- stage inv and inv2 (reuse Act regions), then load weight slices ----
    {
        int* invs  = (int*)Act0;
        int* inv2s = (int*)Act1;
        for (int e = tid; e < SW; e += NTHREADS) invs[e] = d_inv[e];
        __syncthreads();
        for (int e = tid; e < SW; e += NTHREADS) inv2s[e] = invs[invs[e]];
        __syncthreads();
        for (int e = tid; e < JS * SW; e += NTHREADS) {
            int n = e >> 10, q = e & (SW - 1);
            W1pps[n * PADC + q] = __float2bfloat16(LIN_F * W1[(size_t)(jbase + n) * SW + inv2s[q]]);
            Ms[n * PADC + q]    = __float2bfloat16(eps * d_M[(size_t)(jbase + n) * SW + q]);
            W2s[n * PADC + q]   = __float2bfloat16(W2[(size_t)(jbase + n) * SW + q]);
        }
        for (int e = tid; e < JS * IN_W; e += NTHREADS) {
            int n = e >> 8, i = e & (IN_W - 1);
            Xws[n * PADX + i] = __float2bfloat16(W1[(size_t)(jbase + n) * SW + invs[i]]);
        }
        __syncthreads();
    }

    // ---- per-thread static coordinates ----
    const int warp = tid >> 5, lane = tid & 31;
    const int nhalf = warp & 1;
    const int kq    = warp >> 1;
    const int g  = lane >> 2, tc = (lane & 3) * 2;

    const unsigned aOffC = (unsigned)((lane & 15) * (PADC * 2) + ((lane >> 4) << 4) + kq * 512);
    const unsigned aOffX = (unsigned)((lane & 15) * (PADX * 2) + ((lane >> 4) << 4) + kq * 128);
    const unsigned aU  = smem_u32(Act0) + aOffC;
    const unsigned aH  = smem_u32(Act1) + aOffC;
    const unsigned bW1 = smem_u32(W1pps) + aOffC;
    const unsigned bM  = smem_u32(Ms) + aOffC;
    const unsigned bW2 = smem_u32(W2s) + aOffC;
    const unsigned bX  = smem_u32(Xws) + aOffX;
    const unsigned aX0 = smem_u32(XactB) + aOffX;
    const unsigned aX1 = aX0 + (unsigned)(STR * PADX * 2);

    const int j0 = jbase + nhalf * 8 + tc, j1 = j0 + 1;
    const float bb2_0 = b2[j0], bb2_1 = b2[j1];
    const float cf0 = b1[j0] + eps * d_c2[j0];
    const float cf1 = b1[j1] + eps * d_c2[j1];
    const int rp0 = rp[j0], rp1 = rp[j1];
    const bool epi = (kq == 0);
    const bool has_x = (jbase < IN_W);
    const int gA0 = rbase + g, gA1 = rbase + g + 8;          // subtile 0
    const int gB0 = gA0 + STR, gB1 = gA1 + STR;              // subtile 1

    float sp[8], xe[8];

    for (int t = 0; t < SEQ; t++) {
        const int cur = t & 1, nxt = cur ^ 1;
        const bool last = (t == SEQ - 1);
        const __nv_bfloat16* Ug = d_Uh[cur] + (size_t)rbase * SW;
        const __nv_bfloat16* Hg = d_Hh[cur] + (size_t)rbase * SW;

        // ---- subtile 0 copies FIRST (drain overlaps prefetch + x-staging) ----
#pragma unroll
        for (int s = 0; s < 8; s++) {
            int e = tid + s * NTHREADS;
            int row = e >> 7, seg = e & 127;
            unsigned dst = smem_u32(Act0 + row * PADC + seg * 8);
            asm volatile("cp.async.cg.shared.global [%0], [%1], 16;\n"
                         :: "r"(dst), "l"((const void*)(Ug + row * SW + seg * 8)));
        }
        asm volatile("cp.async.commit_group;\n" ::: "memory");
#pragma unroll
        for (int s = 0; s < 8; s++) {
            int e = tid + s * NTHREADS;
            int row = e >> 7, seg = e & 127;
            unsigned dst = smem_u32(Act1 + row * PADC + seg * 8);
            asm volatile("cp.async.cg.shared.global [%0], [%1], 16;\n"
                         :: "r"(dst), "l"((const void*)(Hg + row * SW + seg * 8)));
        }
        asm volatile("cp.async.commit_group;\n" ::: "memory");

        // ---- prefetch epilogue operands (overlaps copy drain) ----
        if (epi) {
            const float* Uc = d_Uf[cur];
            sp[0] = ldcg_f(Uc + gA0 * SW + rp0);
            sp[1] = ldcg_f(Uc + gA0 * SW + rp1);
            sp[2] = ldcg_f(Uc + gA1 * SW + rp0);
            sp[3] = ldcg_f(Uc + gA1 * SW + rp1);
            sp[4] = ldcg_f(Uc + gB0 * SW + rp0);
            sp[5] = ldcg_f(Uc + gB0 * SW + rp1);
            sp[6] = ldcg_f(Uc + gB1 * SW + rp0);
            sp[7] = ldcg_f(Uc + gB1 * SW + rp1);
            if (has_x && !last) {
                const float* xb = x + (size_t)(t + 1) * BATCH * IN_W;
                ld2cg(xe[0], xe[1], xb + gA0 * IN_W + j0);
                ld2cg(xe[2], xe[3], xb + gA1 * IN_W + j0);
                ld2cg(xe[4], xe[5], xb + gB0 * IN_W + j0);
                ld2cg(xe[6], xe[7], xb + gB1 * IN_W + j0);
            }
        }

        // ---- stage x_{t+1} (all 32 rows) fp32->bf16 into Xact (overlaps drain) ----
        if (!last) {
            const float4* xs = (const float4*)(x + (size_t)(t + 1) * BATCH * IN_W
                                               + (size_t)rbase * IN_W);
#pragma unroll
            for (int i = 0; i < 8; i++) {
                int e = tid + i * NTHREADS;      // 0..2047 = 32 rows x 64 float4
                int row = e >> 6, seg = e & 63;
                float4 v = __ldg(xs + row * 64 + seg);
                __nv_bfloat162 p0 = __floats2bfloat162_rn(v.x, v.y);
                __nv_bfloat162 p1 = __floats2bfloat162_rn(v.z, v.w);
                uint32_t* dst = (uint32_t*)(XactB + row * (PADX * 2) + seg * 8);
                dst[0] = *(uint32_t*)&p0;
                dst[1] = *(uint32_t*)&p1;
            }
        }

        float z1[4] = {0,0,0,0}, zy[4] = {0,0,0,0}, yy[4] = {0,0,0,0};
        asm volatile("cp.async.wait_group 1;\n" ::: "memory");
        __syncthreads();                          // u subtile 0 visible (and Xact staged)
        gemmK1024(aU, bW1, nhalf, z1);
        asm volatile("cp.async.wait_group 0;\n" ::: "memory");
        __syncthreads();                          // h subtile 0 visible
        gemmK1024x2(aH, bM, bW2, nhalf, zy, yy);
        if (!last) gemmK256(aX0, bX, nhalf, zy);
        __syncthreads();                          // all reads of Act0/Act1 done

        // ---- subtile 1 copies (overlap with st0 reduce/epilogue) ----
#pragma unroll
        for (int s = 0; s < 8; s++) {
            int e = tid + s * NTHREADS;
            int row = e >> 7, seg = e & 127;
            unsigned dst = smem_u32(Act0 + row * PADC + seg * 8);
            asm volatile("cp.async.cg.shared.global [%0], [%1], 16;\n"
                         :: "r"(dst), "l"((const void*)(Ug + (STR + row) * SW + seg * 8)));
        }
        asm volatile("cp.async.commit_group;\n" ::: "memory");
#pragma unroll
        for (int s = 0; s < 8; s++) {
            int e = tid + s * NTHREADS;
            int row = e >> 7, seg = e & 127;
            unsigned dst = smem_u32(Act1 + row * PADC + seg * 8);
            asm volatile("cp.async.cg.shared.global [%0], [%1], 16;\n"
                         :: "r"(dst), "l"((const void*)(Hg + (STR + row) * SW + seg * 8)));
        }
        asm volatile("cp.async.commit_group;\n" ::: "memory");

        // ---- subtile 0: combine, reduce, epilogue ----
        float zc[4];
#pragma unroll
        for (int u = 0; u < 4; u++) zc[u] = z1[u] + zy[u];   // scales folded into weights
        kreduce8(Red, nhalf, kq, lane, zc, yy);
        if (epi) {
            float nv0 = LIN_F * sp[0] + eps * (yy[0] + bb2_0);
            float nv1 = LIN_F * sp[1] + eps * (yy[1] + bb2_1);
            float nv2 = LIN_F * sp[2] + eps * (yy[2] + bb2_0);
            float nv3 = LIN_F * sp[3] + eps * (yy[3] + bb2_1);
            if (!last) {
                if (has_x) { nv0 += xe[0]; nv1 += xe[1]; nv2 += xe[2]; nv3 += xe[3]; }
                float* Un = d_Uf[nxt];
                __nv_bfloat162* Uhn = (__nv_bfloat162*)d_Uh[nxt];
                __nv_bfloat162* Hhn = (__nv_bfloat162*)d_Hh[nxt];
                st2cg(Un + gA0 * SW + j0, nv0, nv1);
                st2cg(Un + gA1 * SW + j0, nv2, nv3);
                Uhn[(gA0 * SW + j0) >> 1] = __floats2bfloat162_rn(nv0, nv1);
                Uhn[(gA1 * SW + j0) >> 1] = __floats2bfloat162_rn(nv2, nv3);
                float h0 = fmaxf(zc[0] + cf0, 0.f), h1 = fmaxf(zc[1] + cf1, 0.f);
                float h2 = fmaxf(zc[2] + cf0, 0.f), h3 = fmaxf(zc[3] + cf1, 0.f);
                Hhn[(gA0 * SW + j0) >> 1] = __floats2bfloat162_rn(h0, h1);
                Hhn[(gA1 * SW + j0) >> 1] = __floats2bfloat162_rn(h2, h3);
            } else {
                const int rr[4] = { gA0, gA0, gA1, gA1 };
                const int jj[4] = { j0, j1, j0, j1 };
                const float vv[4] = { nv0, nv1, nv2, nv3 };
#pragma unroll
                for (int u = 0; u < 4; u++) {
                    int b = rr[u], i = jj[u]; float v = vv[u];
                    if (out_size == BATCH * (OUT_W + SW)) {
                        out[BATCH * OUT_W + b * SW + i] = v;
                        if (i >= SW - OUT_W) out[b * OUT_W + (i - (SW - OUT_W))] = v;
                    } else if (out_size == BATCH * SW) {
                        out[b * SW + i] = v;
                    } else {
                        if (i >= SW - OUT_W) out[b * OUT_W + (i - (SW - OUT_W))] = v;
                    }
                }
            }
        }

        // ---- subtile 1: GEMMs ----
#pragma unroll
        for (int u = 0; u < 4; u++) { z1[u] = 0.f; zy[u] = 0.f; yy[u] = 0.f; }
        asm volatile("cp.async.wait_group 1;\n" ::: "memory");
        __syncthreads();
        gemmK1024(aU, bW1, nhalf, z1);
        asm volatile("cp.async.wait_group 0;\n" ::: "memory");
        __syncthreads();
        gemmK1024x2(aH, bM, bW2, nhalf, zy, yy);
        if (!last) gemmK256(aX1, bX, nhalf, zy);
#pragma unroll
        for (int u = 0; u < 4; u++) zc[u] = z1[u] + zy[u];
        kreduce8(Red, nhalf, kq, lane, zc, yy);
        if (epi) {
            float nv0 = LIN_F * sp[4] + eps * (yy[0] + bb2_0);
            float nv1 = LIN_F * sp[5] + eps * (yy[1] + bb2_1);
            float nv2 = LIN_F * sp[6] + eps * (yy[2] + bb2_0);
            float nv3 = LIN_F * sp[7] + eps * (yy[3] + bb2_1);
            if (!last) {
                if (has_x) { nv0 += xe[4]; nv1 += xe[5]; nv2 += xe[6]; nv3 += xe[7]; }
                float* Un = d_Uf[nxt];
                __nv_bfloat162* Uhn = (__nv_bfloat162*)d_Uh[nxt];
                __nv_bfloat162* Hhn = (__nv_bfloat162*)d_Hh[nxt];
                st2cg(Un + gB0 * SW + j0, nv0, nv1);
                st2cg(Un + gB1 * SW + j0, nv2, nv3);
                Uhn[(gB0 * SW + j0) >> 1] = __floats2bfloat162_rn(nv0, nv1);
                Uhn[(gB1 * SW + j0) >> 1] = __floats2bfloat162_rn(nv2, nv3);
                float h0 = fmaxf(zc[0] + cf0, 0.f), h1 = fmaxf(zc[1] + cf1, 0.f);
                float h2 = fmaxf(zc[2] + cf0, 0.f), h3 = fmaxf(zc[3] + cf1, 0.f);
                Hhn[(gB0 * SW + j0) >> 1] = __floats2bfloat162_rn(h0, h1);
                Hhn[(gB1 * SW + j0) >> 1] = __floats2bfloat162_rn(h2, h3);
            } else {
                const int rr[4] = { gB0, gB0, gB1, gB1 };
                const int jj[4] = { j0, j1, j0, j1 };
                const float vv[4] = { nv0, nv1, nv2, nv3 };
#pragma unroll
                for (int u = 0; u < 4; u++) {
                    int b = rr[u], i = jj[u]; float v = vv[u];
                    if (out_size == BATCH * (OUT_W + SW)) {
                        out[BATCH * OUT_W + b * SW + i] = v;
                        if (i >= SW - OUT_W) out[b * OUT_W + (i - (SW - OUT_W))] = v;
                    } else if (out_size == BATCH * SW) {
                        out[b * SW + i] = v;
                    } else {
                        if (i >= SW - OUT_W) out[b * OUT_W + (i - (SW - OUT_W))] = v;
                    }
                }
            }
        }

        // ---- single barrier per step ----
        if (!last) {
            bar_arrive(bh, cg);
            bar_wait(bh, (unsigned)(t + 1) * DOM_CTAS);
        }
    }
}

// ---------------- launch ----------------
extern "C" void kernel_launch(void* const* d_in, const int* in_sizes, int n_in,
                              void* d_out, int out_size) {
    const float* x    = (const float*)d_in[0];
    const float* init = (const float*)d_in[1];
    const int*   rp   = (const int*)  d_in[2];
    const float* W1   = (const float*)d_in[3];
    const float* b1   = (const float*)d_in[4];
    const float* W2   = (const float*)d_in[5];
    const float* b2   = (const float*)d_in[6];

    setup0<<<64, 256>>>(x, init, rp);
    setup_rest<<<1216, 256>>>(W1, b1, W2, b2, rp);

    cudaFuncSetAttribute(resrnn_kernel, cudaFuncAttributeMaxDynamicSharedMemorySize, SMEM_TOTAL);
    resrnn_kernel<<<P_CTAS, NTHREADS, SMEM_TOTAL>>>(x, rp, W1, b1, W2, b2,
                                                    (float*)d_out, out_size);
}

// round 16
// speedup vs baseline: 1.0403x; 1.0403x over previous
#include <cuda_runtime.h>
#include <cuda_bf16.h>
#include <cstdint>

// ---------------- problem constants ----------------
#define SEQ    512
#define BATCH  64
#define IN_W   256
#define SW     1024
#define OUT_W  256

// ---------------- kernel config --------------------
#define P_CTAS   128     // 2 row-halves x 64 col-groups
#define DOM_CTAS 64      // arrivals per barrier domain (one half)
#define NTHREADS 256     // 8 warps = 2 n-halves x 4 k-quarters
#define JS       16      // output columns per CTA
#define RWS      32      // batch rows per CTA
#define STR      16      // subtile rows
#define PADC     1032    // padded row stride, K=1024 bufs (2064B = 16 mod 128)
#define PADX     264     // padded row stride, K=256 bufs (528B = 16 mod 128)

#define LIN_F 0.99999f
__device__ __constant__ float EPS_F = (float)(1.0 - 0.99999);

// ---------------- smem byte offsets (total 196608 = 192KB) ----------------
#define W1PP_OFF 0
#define M_OFF    33024
#define W2_OFF   66048
#define XW_OFF   99072
#define ACT0_OFF 107520
#define ACT1_OFF 140544
#define XACT_OFF 173568
#define RED_OFF  190464
#define SMEM_TOTAL 196608

// ---------------- global scratch ----------------
__device__ float          d_Uf[2][BATCH * SW];   // fp32 u_t (ping-pong)
__device__ __nv_bfloat16  d_Uh[2][BATCH * SW];   // bf16 u_t
__device__ __nv_bfloat16  d_Hh[2][BATCH * SW];   // bf16 h_t (ping-pong)
__device__ float          d_M[SW * SW];          // M = W1p @ W2  (fp32, 4MB)
__device__ float          d_c2[SW];              // c2[j] = W1p[j,:]·b2
__device__ int            d_inv[SW];             // inverse permutation
__device__ unsigned       d_cnt[2 * 8 * 64];     // 2 domains x 8 distributed counters

// ---------------- helpers ----------------
static __device__ __forceinline__ unsigned smem_u32(const void* p) {
    return (unsigned)__cvta_generic_to_shared(p);
}

static __device__ __forceinline__ void bar_arrive(int dom, int cg) {
    __syncthreads();
    if (threadIdx.x == 0) {
        unsigned* cnt = d_cnt + dom * 8 * 64 + (cg & 7) * 64;
        asm volatile("red.release.gpu.global.add.u32 [%0], 1;" :: "l"(cnt) : "memory");
    }
}
// MLP-friendly poll: 8 independent relaxed loads per round, acquire fence on exit
static __device__ __forceinline__ void bar_wait(int dom, unsigned target) {
    if (threadIdx.x == 0) {
        unsigned* base = d_cnt + dom * 8 * 64;
        while (true) {
            unsigned v0, v1, v2, v3, v4, v5, v6, v7;
            asm volatile("ld.relaxed.gpu.u32 %0, [%1];" : "=r"(v0) : "l"(base + 0 * 64) : "memory");
            asm volatile("ld.relaxed.gpu.u32 %0, [%1];" : "=r"(v1) : "l"(base + 1 * 64) : "memory");
            asm volatile("ld.relaxed.gpu.u32 %0, [%1];" : "=r"(v2) : "l"(base + 2 * 64) : "memory");
            asm volatile("ld.relaxed.gpu.u32 %0, [%1];" : "=r"(v3) : "l"(base + 3 * 64) : "memory");
            asm volatile("ld.relaxed.gpu.u32 %0, [%1];" : "=r"(v4) : "l"(base + 4 * 64) : "memory");
            asm volatile("ld.relaxed.gpu.u32 %0, [%1];" : "=r"(v5) : "l"(base + 5 * 64) : "memory");
            asm volatile("ld.relaxed.gpu.u32 %0, [%1];" : "=r"(v6) : "l"(base + 6 * 64) : "memory");
            asm volatile("ld.relaxed.gpu.u32 %0, [%1];" : "=r"(v7) : "l"(base + 7 * 64) : "memory");
            unsigned total = v0 + v1 + v2 + v3 + v4 + v5 + v6 + v7;
            if (total >= target) break;
        }
        asm volatile("fence.acq_rel.gpu;" ::: "memory");
    }
    __syncthreads();
}

static __device__ __forceinline__ void ldsm4(uint32_t& r0, uint32_t& r1, uint32_t& r2, uint32_t& r3,
                                             unsigned addr) {
    asm volatile("ldmatrix.sync.aligned.m8n8.x4.shared.b16 {%0,%1,%2,%3}, [%4];"
                 : "=r"(r0), "=r"(r1), "=r"(r2), "=r"(r3) : "r"(addr));
}
static __device__ __forceinline__ void mma16816(float* c,
                                                uint32_t a0, uint32_t a1, uint32_t a2, uint32_t a3,
                                                uint32_t b0, uint32_t b1) {
    asm("mma.sync.aligned.m16n8k16.row.col.f32.bf16.bf16.f32 "
        "{%0,%1,%2,%3}, {%4,%5,%6,%7}, {%8,%9}, {%0,%1,%2,%3};\n"
        : "+f"(c[0]), "+f"(c[1]), "+f"(c[2]), "+f"(c[3])
        : "r"(a0), "r"(a1), "r"(a2), "r"(a3), "r"(b0), "r"(b1));
}
static __device__ __forceinline__ void ld2cg(float& a, float& b, const float* p) {
    asm volatile("ld.global.cg.v2.f32 {%0,%1}, [%2];" : "=f"(a), "=f"(b) : "l"(p));
}
static __device__ __forceinline__ float ldcg_f(const float* p) {
    float v;
    asm volatile("ld.global.cg.f32 %0, [%1];" : "=f"(v) : "l"(p));
    return v;
}
static __device__ __forceinline__ void st2cg(float* p, float a, float b) {
    asm volatile("st.global.cg.v2.f32 [%0], {%1,%2};" :: "l"(p), "f"(a), "f"(b));
}

// K=1024 GEMM (per-warp K=256), dual accumulators
static __device__ __forceinline__ void gemmK1024(unsigned aA, unsigned aB, int nhalf, float* acc) {
    float acc2[4] = {0.f, 0.f, 0.f, 0.f};
#pragma unroll
    for (int ki = 0; ki < 16; ki += 2) {
        uint32_t a0,a1,a2,a3,b0,b1,b2,b3;
        ldsm4(a0,a1,a2,a3, aA + ki*32);
        ldsm4(b0,b1,b2,b3, aB + ki*32);
        if (nhalf == 0) mma16816(acc, a0,a1,a2,a3, b0,b2);
        else            mma16816(acc, a0,a1,a2,a3, b1,b3);
        ldsm4(a0,a1,a2,a3, aA + (ki+1)*32);
        ldsm4(b0,b1,b2,b3, aB + (ki+1)*32);
        if (nhalf == 0) mma16816(acc2, a0,a1,a2,a3, b0,b2);
        else            mma16816(acc2, a0,a1,a2,a3, b1,b3);
    }
#pragma unroll
    for (int u = 0; u < 4; u++) acc[u] += acc2[u];
}

// K=1024 GEMM with shared A and two B matrices (M, W2) -> two accumulators (single-acc, reg-lean)
static __device__ __forceinline__ void gemmK1024x2(unsigned aA, unsigned bM, unsigned bW,
                                                   int nhalf, float* zy, float* yy) {
#pragma unroll
    for (int ki = 0; ki < 16; ki++) {
        uint32_t a0,a1,a2,a3, m0,m1,m2,m3, w0,w1,w2,w3;
        ldsm4(a0,a1,a2,a3, aA + ki*32);
        ldsm4(m0,m1,m2,m3, bM + ki*32);
        ldsm4(w0,w1,w2,w3, bW + ki*32);
        if (nhalf == 0) { mma16816(zy, a0,a1,a2,a3, m0,m2); mma16816(yy, a0,a1,a2,a3, w0,w2); }
        else            { mma16816(zy, a0,a1,a2,a3, m1,m3); mma16816(yy, a0,a1,a2,a3, w1,w3); }
    }
}

// K=256 GEMM (x-term), accumulate into zy
static __device__ __forceinline__ void gemmK256(unsigned aA, unsigned aB, int nhalf, float* zy) {
#pragma unroll
    for (int ki = 0; ki < 4; ki++) {
        uint32_t a0,a1,a2,a3,b0,b1,b2,b3;
        ldsm4(a0,a1,a2,a3, aA + ki*32);
        ldsm4(b0,b1,b2,b3, aB + ki*32);
        if (nhalf == 0) mma16816(zy, a0,a1,a2,a3, b0,b2);
        else            mma16816(zy, a0,a1,a2,a3, b1,b3);
    }
}

// 4-way k-reduction of (z[4], y[4])
static __device__ __forceinline__ void kreduce8(float* Red, int nhalf, int kq, int lane,
                                                float* z, float* y) {
    if (kq > 0) {
        float* s = Red + ((kq - 1) * 2 + nhalf) * 256;
#pragma unroll
        for (int u = 0; u < 4; u++) { s[u*32 + lane] = z[u]; s[(u+4)*32 + lane] = y[u]; }
    }
    __syncthreads();
    if (kq == 0) {
#pragma unroll
        for (int k = 0; k < 3; k++) {
            const float* s = Red + (k * 2 + nhalf) * 256;
#pragma unroll
            for (int u = 0; u < 4; u++) { z[u] += s[u*32 + lane]; y[u] += s[(u+4)*32 + lane]; }
        }
    }
}

// copy helper: 16 rows x 2KB from global bf16 into padded smem via cp.async
static __device__ __forceinline__ void copy_tile(__nv_bfloat16* dstBase,
                                                 const __nv_bfloat16* __restrict__ src,
                                                 int tid) {
#pragma unroll
    for (int s = 0; s < 8; s++) {
        int e = tid + s * NTHREADS;
        int row = e >> 7, seg = e & 127;
        unsigned dst = smem_u32(dstBase + row * PADC + seg * 8);
        asm volatile("cp.async.cg.shared.global [%0], [%1], 16;\n"
                     :: "r"(dst), "l"((const void*)(src + row * SW + seg * 8)));
    }
    asm volatile("cp.async.commit_group;\n" ::: "memory");
}

// ---------------- setup 0: inv, u0, counters ----------------
__global__ void setup0(const float* __restrict__ x, const float* __restrict__ init,
                       const int* __restrict__ rp) {
    int tid = blockIdx.x * blockDim.x + threadIdx.x;
    if (tid < 2 * 8 * 64) d_cnt[tid] = 0u;
    if (tid < SW) d_inv[rp[tid]] = tid;
    const float eps = EPS_F;
    for (int e = tid; e < BATCH * SW; e += gridDim.x * blockDim.x) {
        int b = e >> 10, p = e & (SW - 1);
        float v = eps * init[p];
        if (p < IN_W) v += x[b * IN_W + p];
        d_Uf[0][b * SW + p] = v;
        d_Uh[0][b * SW + p] = __float2bfloat16(v);
    }
}

// ---------------- fused setup: M (blocks 0-1023), h0 (1024-1087), c2 (1088-1215) ----
__global__ void setup_rest(const float* __restrict__ W1, const float* __restrict__ b1,
                           const float* __restrict__ W2, const float* __restrict__ b2,
                           const int* __restrict__ rp) {
    __shared__ float As[32][33], Bs[32][33];
    const int bid = blockIdx.x;
    const int tx = threadIdx.x & 15, ty = threadIdx.x >> 4;
    const int lin = threadIdx.x;

    if (bid < 1024) {
        int jb = (bid >> 5) * 32, mb = (bid & 31) * 32;
        float acc00 = 0.f, acc01 = 0.f, acc10 = 0.f, acc11 = 0.f;
        for (int kc = 0; kc < 32; kc++) {
#pragma unroll
            for (int i = 0; i < 4; i++) {
                int e = lin + i * 256;
                int r = e >> 5, c = e & 31;
                As[r][c] = W1[(size_t)(jb + r) * SW + kc * 32 + c];
                Bs[r][c] = W2[(size_t)rp[kc * 32 + r] * SW + mb + c];
            }
            __syncthreads();
#pragma unroll
            for (int kk = 0; kk < 32; kk++) {
                float a0 = As[ty * 2][kk], a1 = As[ty * 2 + 1][kk];
                float b0 = Bs[kk][tx * 2], b1 = Bs[kk][tx * 2 + 1];
                acc00 += a0 * b0; acc01 += a0 * b1;
                acc10 += a1 * b0; acc11 += a1 * b1;
            }
            __syncthreads();
        }
        d_M[(size_t)(jb + ty * 2)     * SW + mb + tx * 2]     = acc00;
        d_M[(size_t)(jb + ty * 2)     * SW + mb + tx * 2 + 1] = acc01;
        d_M[(size_t)(jb + ty * 2 + 1) * SW + mb + tx * 2]     = acc10;
        d_M[(size_t)(jb + ty * 2 + 1) * SW + mb + tx * 2 + 1] = acc11;
    } else if (bid < 1088) {
        int lb = bid - 1024;
        int bb = (lb >> 5) * 32, jb = (lb & 31) * 32;
        float acc00 = 0.f, acc01 = 0.f, acc10 = 0.f, acc11 = 0.f;
        for (int kc = 0; kc < 32; kc++) {
#pragma unroll
            for (int i = 0; i < 4; i++) {
                int e = lin + i * 256;
                int r = e >> 5, c = e & 31;
                As[r][c] = d_Uf[0][(size_t)(bb + r) * SW + rp[kc * 32 + c]];
                Bs[r][c] = W1[(size_t)(jb + r) * SW + kc * 32 + c];
            }
            __syncthreads();
#pragma unroll
            for (int kk = 0; kk < 32; kk++) {
                float a0 = As[ty * 2][kk], a1 = As[ty * 2 + 1][kk];
                float b0 = Bs[tx * 2][kk], b1 = Bs[tx * 2 + 1][kk];
                acc00 += a0 * b0; acc01 += a0 * b1;
                acc10 += a1 * b0; acc11 += a1 * b1;
            }
            __syncthreads();
        }
        int j0 = jb + tx * 2, j1 = j0 + 1;
        d_Hh[0][(size_t)(bb + ty*2)     * SW + j0] = __float2bfloat16(fmaxf(acc00 + b1[j0], 0.f));
        d_Hh[0][(size_t)(bb + ty*2)     * SW + j1] = __float2bfloat16(fmaxf(acc01 + b1[j1], 0.f));
        d_Hh[0][(size_t)(bb + ty*2 + 1) * SW + j0] = __float2bfloat16(fmaxf(acc10 + b1[j0], 0.f));
        d_Hh[0][(size_t)(bb + ty*2 + 1) * SW + j1] = __float2bfloat16(fmaxf(acc11 + b1[j1], 0.f));
    } else {
        float* pb2 = &As[0][0];
        for (int k = lin; k < SW; k += 256) pb2[k] = b2[rp[k]];
        __syncthreads();
        int warp = lin >> 5, lane = lin & 31;
        int j = (bid - 1088) * 8 + warp;
        float acc = 0.f;
        for (int i = lane; i < SW; i += 32) acc += W1[(size_t)j * SW + i] * pb2[i];
#pragma unroll
        for (int o = 16; o > 0; o >>= 1) acc += __shfl_down_sync(0xffffffff, acc, o);
        if (lane == 0) d_c2[j] = acc;
    }
}

// ---------------- persistent one-barrier-per-step RNN kernel ----------------
__global__ void __launch_bounds__(NTHREADS)
resrnn_kernel(const float* __restrict__ x, const int* __restrict__ rp,
              const float* __restrict__ W1, const float* __restrict__ b1,
              const float* __restrict__ W2, const float* __restrict__ b2,
              float* __restrict__ out, int out_size) {
    extern __shared__ char smem[];
    __nv_bfloat16* W1pps = (__nv_bfloat16*)(smem + W1PP_OFF);  // [16][PADC]
    __nv_bfloat16* Ms    = (__nv_bfloat16*)(smem + M_OFF);     // [16][PADC]
    __nv_bfloat16* W2s   = (__nv_bfloat16*)(smem + W2_OFF);    // [16][PADC]
    __nv_bfloat16* Xws   = (__nv_bfloat16*)(smem + XW_OFF);    // [16][PADX]
    __nv_bfloat16* Act0  = (__nv_bfloat16*)(smem + ACT0_OFF);  // [16][PADC] (u subtile)
    __nv_bfloat16* Act1  = (__nv_bfloat16*)(smem + ACT1_OFF);  // [16][PADC] (h subtile)
    char*          XactB = smem + XACT_OFF;                     // [32][PADX] bf16
    float*         Red   = (float*)(smem + RED_OFF);            // [6][256]

    const int tid   = threadIdx.x;
    const int cta   = blockIdx.x;
    const int cg    = cta & 63;
    const int bh    = cta >> 6;                 // row half = barrier domain
    const int jbase = cg * JS;
    const int rbase = bh * RWS;
    const float eps = EPS_F;
    const float inv_eps = 1.0f / eps;

    // ---- stage inv and inv2 (reuse Act regions), then load weight slices ----
    {
        int* invs  = (int*)Act0;
        int* inv2s = (int*)Act1;
        for (int e = tid; e < SW; e += NTHREADS) invs[e] = d_inv[e];
        __syncthreads();
        for (int e = tid; e < SW; e += NTHREADS) inv2s[e] = invs[invs[e]];
        __syncthreads();
        for (int e = tid; e < JS * SW; e += NTHREADS) {
            int n = e >> 10, q = e & (SW - 1);
            W1pps[n * PADC + q] = __float2bfloat16(W1[(size_t)(jbase + n) * SW + inv2s[q]]);
            Ms[n * PADC + q]    = __float2bfloat16(d_M[(size_t)(jbase + n) * SW + q]);
            W2s[n * PADC + q]   = __float2bfloat16(W2[(size_t)(jbase + n) * SW + q]);
        }
        for (int e = tid; e < JS * IN_W; e += NTHREADS) {
            int n = e >> 8, i = e & (IN_W - 1);
            Xws[n * PADX + i] = __float2bfloat16(W1[(size_t)(jbase + n) * SW + invs[i]] * inv_eps);
        }
        __syncthreads();
    }

    // ---- per-thread static coordinates ----
    const int warp = tid >> 5, lane = tid & 31;
    const int nhalf = warp & 1;
    const int kq    = warp >> 1;
    const int g  = lane >> 2, tc = (lane & 3) * 2;

    const unsigned aOffC = (unsigned)((lane & 15) * (PADC * 2) + ((lane >> 4) << 4) + kq * 512);
    const unsigned aOffX = (unsigned)((lane & 15) * (PADX * 2) + ((lane >> 4) << 4) + kq * 128);
    const unsigned aU  = smem_u32(Act0) + aOffC;
    const unsigned aH  = smem_u32(Act1) + aOffC;
    const unsigned bW1 = smem_u32(W1pps) + aOffC;
    const unsigned bM  = smem_u32(Ms) + aOffC;
    const unsigned bW2 = smem_u32(W2s) + aOffC;
    const unsigned bX  = smem_u32(Xws) + aOffX;
    const unsigned aX0 = smem_u32(XactB) + aOffX;
    const unsigned aX1 = aX0 + (unsigned)(STR * PADX * 2);

    const int j0 = jbase + nhalf * 8 + tc, j1 = j0 + 1;
    const float bb2_0 = b2[j0], bb2_1 = b2[j1];
    const float cf0 = b1[j0] + eps * d_c2[j0];
    const float cf1 = b1[j1] + eps * d_c2[j1];
    const int rp0 = rp[j0], rp1 = rp[j1];
    const bool epi = (kq == 0);
    const bool has_x = (jbase < IN_W);
    const int gA0 = rbase + g, gA1 = rbase + g + 8;          // subtile 0
    const int gB0 = gA0 + STR, gB1 = gA1 + STR;              // subtile 1

    float sp[8], xe[8];

    for (int t = 0; t < SEQ; t++) {
        const int cur = t & 1, nxt = cur ^ 1;
        const bool last = (t == SEQ - 1);
        const __nv_bfloat16* Ug = d_Uh[cur] + (size_t)rbase * SW;
        const __nv_bfloat16* Hg = d_Hh[cur] + (size_t)rbase * SW;

        // ---- prefetch epilogue operands ----
        if (epi) {
            const float* Uc = d_Uf[cur];
            sp[0] = ldcg_f(Uc + gA0 * SW + rp0);
            sp[1] = ldcg_f(Uc + gA0 * SW + rp1);
            sp[2] = ldcg_f(Uc + gA1 * SW + rp0);
            sp[3] = ldcg_f(Uc + gA1 * SW + rp1);
            sp[4] = ldcg_f(Uc + gB0 * SW + rp0);
            sp[5] = ldcg_f(Uc + gB0 * SW + rp1);
            sp[6] = ldcg_f(Uc + gB1 * SW + rp0);
            sp[7] = ldcg_f(Uc + gB1 * SW + rp1);
            if (has_x && !last) {
                const float* xb = x + (size_t)(t + 1) * BATCH * IN_W;
                ld2cg(xe[0], xe[1], xb + gA0 * IN_W + j0);
                ld2cg(xe[2], xe[3], xb + gA1 * IN_W + j0);
                ld2cg(xe[4], xe[5], xb + gB0 * IN_W + j0);
                ld2cg(xe[6], xe[7], xb + gB1 * IN_W + j0);
            }
        }

        // ---- stage x_{t+1} (all 32 rows) fp32->bf16 into Xact ----
        if (!last) {
            const float4* xs = (const float4*)(x + (size_t)(t + 1) * BATCH * IN_W
                                               + (size_t)rbase * IN_W);
#pragma unroll
            for (int i = 0; i < 8; i++) {
                int e = tid + i * NTHREADS;      // 0..2047 = 32 rows x 64 float4
                int row = e >> 6, seg = e & 63;
                float4 v = __ldg(xs + row * 64 + seg);
                __nv_bfloat162 p0 = __floats2bfloat162_rn(v.x, v.y);
                __nv_bfloat162 p1 = __floats2bfloat162_rn(v.z, v.w);
                uint32_t* dst = (uint32_t*)(XactB + row * (PADX * 2) + seg * 8);
                dst[0] = *(uint32_t*)&p0;
                dst[1] = *(uint32_t*)&p1;
            }
        }

        // ---- issue subtile-0 copies ----
        copy_tile(Act0, Ug, tid);                  // group: U0
        copy_tile(Act1, Hg, tid);                  // group: H0

        float z1[4] = {0,0,0,0}, zy[4] = {0,0,0,0}, yy[4] = {0,0,0,0};
        asm volatile("cp.async.wait_group 1;\n" ::: "memory");   // U0 done
        __syncthreads();                          // u subtile 0 visible (and Xact staged)
        gemmK1024(aU, bW1, nhalf, z1);
        __syncthreads();                          // all warps done reading Act0

        // ---- issue U1 copy into Act0 (drains under gemmH0x2) ----
        copy_tile(Act0, Ug + STR * SW, tid);       // group: U1

        asm volatile("cp.async.wait_group 1;\n" ::: "memory");   // H0 done (U1 pending)
        __syncthreads();                          // h subtile 0 visible
        gemmK1024x2(aH, bM, bW2, nhalf, zy, yy);
        if (!last) gemmK256(aX0, bX, nhalf, zy);
        __syncthreads();                          // all warps done reading Act1

        // ---- issue H1 copy into Act1 (drains under reduce/epilogue) ----
        copy_tile(Act1, Hg + STR * SW, tid);       // group: H1

        // ---- subtile 0: combine, reduce, epilogue ----
        float zc[4];
#pragma unroll
        for (int u = 0; u < 4; u++) zc[u] = LIN_F * z1[u] + eps * zy[u];
        kreduce8(Red, nhalf, kq, lane, zc, yy);
        if (epi) {
            float nv0 = LIN_F * sp[0] + eps * (yy[0] + bb2_0);
            float nv1 = LIN_F * sp[1] + eps * (yy[1] + bb2_1);
            float nv2 = LIN_F * sp[2] + eps * (yy[2] + bb2_0);
            float nv3 = LIN_F * sp[3] + eps * (yy[3] + bb2_1);
            if (!last) {
                if (has_x) { nv0 += xe[0]; nv1 += xe[1]; nv2 += xe[2]; nv3 += xe[3]; }
                float* Un = d_Uf[nxt];
                __nv_bfloat162* Uhn = (__nv_bfloat162*)d_Uh[nxt];
                __nv_bfloat162* Hhn = (__nv_bfloat162*)d_Hh[nxt];
                st2cg(Un + gA0 * SW + j0, nv0, nv1);
                st2cg(Un + gA1 * SW + j0, nv2, nv3);
                Uhn[(gA0 * SW + j0) >> 1] = __floats2bfloat162_rn(nv0, nv1);
                Uhn[(gA1 * SW + j0) >> 1] = __floats2bfloat162_rn(nv2, nv3);
                float h0 = fmaxf(zc[0] + cf0, 0.f), h1 = fmaxf(zc[1] + cf1, 0.f);
                float h2 = fmaxf(zc[2] + cf0, 0.f), h3 = fmaxf(zc[3] + cf1, 0.f);
                Hhn[(gA0 * SW + j0) >> 1] = __floats2bfloat162_rn(h0, h1);
                Hhn[(gA1 * SW + j0) >> 1] = __floats2bfloat162_rn(h2, h3);
            } else {
                const int rr[4] = { gA0, gA0, gA1, gA1 };
                const int jj[4] = { j0, j1, j0, j1 };
                const float vv[4] = { nv0, nv1, nv2, nv3 };
#pragma unroll
                for (int u = 0; u < 4; u++) {
                    int b = rr[u], i = jj[u]; float v = vv[u];
                    if (out_size == BATCH * (OUT_W + SW)) {
                        out[BATCH * OUT_W + b * SW + i] = v;
                        if (i >= SW - OUT_W) out[b * OUT_W + (i - (SW - OUT_W))] = v;
                    } else if (out_size == BATCH * SW) {
                        out[b * SW + i] = v;
                    } else {
                        if (i >= SW - OUT_W) out[b * OUT_W + (i - (SW - OUT_W))] = v;
                    }
                }
            }
        }

        // ---- subtile 1: GEMMs ----
#pragma unroll
        for (int u = 0; u < 4; u++) { z1[u] = 0.f; zy[u] = 0.f; yy[u] = 0.f; }
        asm volatile("cp.async.wait_group 1;\n" ::: "memory");   // U1 done (H1 pending)
        __syncthreads();
        gemmK1024(aU, bW1, nhalf, z1);
        asm volatile("cp.async.wait_group 0;\n" ::: "memory");   // H1 done
        __syncthreads();
        gemmK1024x2(aH, bM, bW2, nhalf, zy, yy);
        if (!last) gemmK256(aX1, bX, nhalf, zy);
#pragma unroll
        for (int u = 0; u < 4; u++) zc[u] = LIN_F * z1[u] + eps * zy[u];
        kreduce8(Red, nhalf, kq, lane, zc, yy);
        if (epi) {
            float nv0 = LIN_F * sp[4] + eps * (yy[0] + bb2_0);
            float nv1 = LIN_F * sp[5] + eps * (yy[1] + bb2_1);
            float nv2 = LIN_F * sp[6] + eps * (yy[2] + bb2_0);
            float nv3 = LIN_F * sp[7] + eps * (yy[3] + bb2_1);
            if (!last) {
                if (has_x) { nv0 += xe[4]; nv1 += xe[5]; nv2 += xe[6]; nv3 += xe[7]; }
                float* Un = d_Uf[nxt];
                __nv_bfloat162* Uhn = (__nv_bfloat162*)d_Uh[nxt];
                __nv_bfloat162* Hhn = (__nv_bfloat162*)d_Hh[nxt];
                st2cg(Un + gB0 * SW + j0, nv0, nv1);
                st2cg(Un + gB1 * SW + j0, nv2, nv3);
                Uhn[(gB0 * SW + j0) >> 1] = __floats2bfloat162_rn(nv0, nv1);
                Uhn[(gB1 * SW + j0) >> 1] = __floats2bfloat162_rn(nv2, nv3);
                float h0 = fmaxf(zc[0] + cf0, 0.f), h1 = fmaxf(zc[1] + cf1, 0.f);
                float h2 = fmaxf(zc[2] + cf0, 0.f), h3 = fmaxf(zc[3] + cf1, 0.f);
                Hhn[(gB0 * SW + j0) >> 1] = __floats2bfloat162_rn(h0, h1);
                Hhn[(gB1 * SW + j0) >> 1] = __floats2bfloat162_rn(h2, h3);
            } else {
                const int rr[4] = { gB0, gB0, gB1, gB1 };
                const int jj[4] = { j0, j1, j0, j1 };
                const float vv[4] = { nv0, nv1, nv2, nv3 };
#pragma unroll
                for (int u = 0; u < 4; u++) {
                    int b = rr[u], i = jj[u]; float v = vv[u];
                    if (out_size == BATCH * (OUT_W + SW)) {
                        out[BATCH * OUT_W + b * SW + i] = v;
                        if (i >= SW - OUT_W) out[b * OUT_W + (i - (SW - OUT_W))] = v;
                    } else if (out_size == BATCH * SW) {
                        out[b * SW + i] = v;
                    } else {
                        if (i >= SW - OUT_W) out[b * OUT_W + (i - (SW - OUT_W))] = v;
                    }
                }
            }
        }

        // ---- single barrier per step ----
        if (!last) {
            bar_arrive(bh, cg);
            bar_wait(bh, (unsigned)(t + 1) * DOM_CTAS);
        }
    }
}

// ---------------- launch ----------------
extern "C" void kernel_launch(void* const* d_in, const int* in_sizes, int n_in,
                              void* d_out, int out_size) {
    const float* x    = (const float*)d_in[0];
    const float* init = (const float*)d_in[1];
    const int*   rp   = (const int*)  d_in[2];
    const float* W1   = (const float*)d_in[3];
    const float* b1   = (const float*)d_in[4];
    const float* W2   = (const float*)d_in[5];
    const float* b2   = (const float*)d_in[6];

    setup0<<<64, 256>>>(x, init, rp);
    setup_rest<<<1216, 256>>>(W1, b1, W2, b2, rp);

    cudaFuncSetAttribute(resrnn_kernel, cudaFuncAttributeMaxDynamicSharedMemorySize, SMEM_TOTAL);
    resrnn_kernel<<<P_CTAS, NTHREADS, SMEM_TOTAL>>>(x, rp, W1, b1, W2, b2,
                                                    (float*)d_out, out_size);
}

// round 17
// speedup vs baseline: 1.1805x; 1.1348x over previous
#include <cuda_runtime.h>
#include <cuda_bf16.h>
#include <cstdint>

// ---------------- problem constants ----------------
#define SEQ    512
#define BATCH  64
#define IN_W   256
#define SW     1024
#define OUT_W  256

// ---------------- kernel config --------------------
#define P_CTAS   128     // 2 row-halves x 64 col-groups
#define DOM_CTAS 64      // arrivals per barrier domain (one half)
#define NTHREADS 256     // 8 warps = 2 n-halves x 4 k-quarters
#define JS       16      // output columns per CTA
#define RWS      32      // batch rows per CTA
#define STR      16      // subtile rows
#define PADC     1032    // padded row stride, K=1024 bufs (2064B = 16 mod 128)
#define PADX     264     // padded row stride, K=256 bufs (528B = 16 mod 128)

#define LIN_F 0.99999f
__device__ __constant__ float EPS_F = (float)(1.0 - 0.99999);

// ---------------- smem byte offsets (total 196608 = 192KB) ----------------
#define W1PP_OFF 0
#define M_OFF    33024
#define W2_OFF   66048
#define XW_OFF   99072
#define ACT0_OFF 107520
#define ACT1_OFF 140544
#define XACT_OFF 173568
#define RED_OFF  190464
#define SMEM_TOTAL 196608

// ---------------- global scratch ----------------
__device__ float          d_Uf[2][BATCH * SW];   // fp32 u_t (ping-pong)
__device__ __nv_bfloat16  d_Uh[2][BATCH * SW];   // bf16 u_t
__device__ __nv_bfloat16  d_Hh[2][BATCH * SW];   // bf16 h_t (ping-pong)
__device__ float          d_M[SW * SW];          // M = W1p @ W2  (fp32, 4MB)
__device__ float          d_c2[SW];              // c2[j] = W1p[j,:]·b2
__device__ int            d_inv[SW];             // inverse permutation
__device__ unsigned       d_cnt[2 * 8 * 64];     // 2 domains x 8 distributed counters

// ---------------- helpers ----------------
static __device__ __forceinline__ unsigned smem_u32(const void* p) {
    return (unsigned)__cvta_generic_to_shared(p);
}

static __device__ __forceinline__ void bar_arrive(int dom, int cg) {
    __syncthreads();
    if (threadIdx.x == 0) {
        unsigned* cnt = d_cnt + dom * 8 * 64 + (cg & 7) * 64;
        asm volatile("red.release.gpu.global.add.u32 [%0], 1;" :: "l"(cnt) : "memory");
    }
}
// MLP-friendly poll: 8 independent relaxed loads per round, acquire fence on exit
static __device__ __forceinline__ void bar_wait(int dom, unsigned target) {
    if (threadIdx.x == 0) {
        unsigned* base = d_cnt + dom * 8 * 64;
        while (true) {
            unsigned v0, v1, v2, v3, v4, v5, v6, v7;
            asm volatile("ld.relaxed.gpu.u32 %0, [%1];" : "=r"(v0) : "l"(base + 0 * 64) : "memory");
            asm volatile("ld.relaxed.gpu.u32 %0, [%1];" : "=r"(v1) : "l"(base + 1 * 64) : "memory");
            asm volatile("ld.relaxed.gpu.u32 %0, [%1];" : "=r"(v2) : "l"(base + 2 * 64) : "memory");
            asm volatile("ld.relaxed.gpu.u32 %0, [%1];" : "=r"(v3) : "l"(base + 3 * 64) : "memory");
            asm volatile("ld.relaxed.gpu.u32 %0, [%1];" : "=r"(v4) : "l"(base + 4 * 64) : "memory");
            asm volatile("ld.relaxed.gpu.u32 %0, [%1];" : "=r"(v5) : "l"(base + 5 * 64) : "memory");
            asm volatile("ld.relaxed.gpu.u32 %0, [%1];" : "=r"(v6) : "l"(base + 6 * 64) : "memory");
            asm volatile("ld.relaxed.gpu.u32 %0, [%1];" : "=r"(v7) : "l"(base + 7 * 64) : "memory");
            unsigned total = v0 + v1 + v2 + v3 + v4 + v5 + v6 + v7;
            if (total >= target) break;
        }
        asm volatile("fence.acq_rel.gpu;" ::: "memory");
    }
    __syncthreads();
}

static __device__ __forceinline__ void ldsm4(uint32_t& r0, uint32_t& r1, uint32_t& r2, uint32_t& r3,
                                             unsigned addr) {
    asm volatile("ldmatrix.sync.aligned.m8n8.x4.shared.b16 {%0,%1,%2,%3}, [%4];"
                 : "=r"(r0), "=r"(r1), "=r"(r2), "=r"(r3) : "r"(addr));
}
static __device__ __forceinline__ void mma16816(float* c,
                                                uint32_t a0, uint32_t a1, uint32_t a2, uint32_t a3,
                                                uint32_t b0, uint32_t b1) {
    asm("mma.sync.aligned.m16n8k16.row.col.f32.bf16.bf16.f32 "
        "{%0,%1,%2,%3}, {%4,%5,%6,%7}, {%8,%9}, {%0,%1,%2,%3};\n"
        : "+f"(c[0]), "+f"(c[1]), "+f"(c[2]), "+f"(c[3])
        : "r"(a0), "r"(a1), "r"(a2), "r"(a3), "r"(b0), "r"(b1));
}
static __device__ __forceinline__ void ld2cg(float& a, float& b, const float* p) {
    asm volatile("ld.global.cg.v2.f32 {%0,%1}, [%2];" : "=f"(a), "=f"(b) : "l"(p));
}
static __device__ __forceinline__ float ldcg_f(const float* p) {
    float v;
    asm volatile("ld.global.cg.f32 %0, [%1];" : "=f"(v) : "l"(p));
    return v;
}
static __device__ __forceinline__ void st2cg(float* p, float a, float b) {
    asm volatile("st.global.cg.v2.f32 [%0], {%1,%2};" :: "l"(p), "f"(a), "f"(b));
}

// ---- B loads are warp-specialized: one ldsm4 covers this warp's 8 rows x 2 k-steps ----

// K=1024 GEMM (per-warp K=256), dual accumulators, half-B loads
static __device__ __forceinline__ void gemmK1024(unsigned aA, unsigned aB, float* acc) {
    float acc2[4] = {0.f, 0.f, 0.f, 0.f};
#pragma unroll
    for (int kp = 0; kp < 8; kp++) {
        uint32_t b0,b1,b2,b3, a0,a1,a2,a3;
        ldsm4(b0,b1,b2,b3, aB + kp*64);            // 2 k-steps of B (8 rows)
        ldsm4(a0,a1,a2,a3, aA + (2*kp)*32);
        mma16816(acc, a0,a1,a2,a3, b0,b1);
        ldsm4(a0,a1,a2,a3, aA + (2*kp+1)*32);
        mma16816(acc2, a0,a1,a2,a3, b2,b3);
    }
#pragma unroll
    for (int u = 0; u < 4; u++) acc[u] += acc2[u];
}

// K=1024 GEMM, shared A, two B matrices (M, W2), half-B loads
static __device__ __forceinline__ void gemmK1024x2(unsigned aA, unsigned bM, unsigned bW,
                                                   float* zy, float* yy) {
#pragma unroll
    for (int kp = 0; kp < 8; kp++) {
        uint32_t m0,m1,m2,m3, w0,w1,w2,w3, a0,a1,a2,a3;
        ldsm4(m0,m1,m2,m3, bM + kp*64);
        ldsm4(w0,w1,w2,w3, bW + kp*64);
        ldsm4(a0,a1,a2,a3, aA + (2*kp)*32);
        mma16816(zy, a0,a1,a2,a3, m0,m1);
        mma16816(yy, a0,a1,a2,a3, w0,w1);
        ldsm4(a0,a1,a2,a3, aA + (2*kp+1)*32);
        mma16816(zy, a0,a1,a2,a3, m2,m3);
        mma16816(yy, a0,a1,a2,a3, w2,w3);
    }
}

// K=256 GEMM (x-term, per-warp K=64), half-B loads
static __device__ __forceinline__ void gemmK256(unsigned aA, unsigned aB, float* zy) {
#pragma unroll
    for (int kp = 0; kp < 2; kp++) {
        uint32_t b0,b1,b2,b3, a0,a1,a2,a3;
        ldsm4(b0,b1,b2,b3, aB + kp*64);
        ldsm4(a0,a1,a2,a3, aA + (2*kp)*32);
        mma16816(zy, a0,a1,a2,a3, b0,b1);
        ldsm4(a0,a1,a2,a3, aA + (2*kp+1)*32);
        mma16816(zy, a0,a1,a2,a3, b2,b3);
    }
}

// 4-way k-reduction of (z[4], y[4])
static __device__ __forceinline__ void kreduce8(float* Red, int nhalf, int kq, int lane,
                                                float* z, float* y) {
    if (kq > 0) {
        float* s = Red + ((kq - 1) * 2 + nhalf) * 256;
#pragma unroll
        for (int u = 0; u < 4; u++) { s[u*32 + lane] = z[u]; s[(u+4)*32 + lane] = y[u]; }
    }
    __syncthreads();
    if (kq == 0) {
#pragma unroll
        for (int k = 0; k < 3; k++) {
            const float* s = Red + (k * 2 + nhalf) * 256;
#pragma unroll
            for (int u = 0; u < 4; u++) { z[u] += s[u*32 + lane]; y[u] += s[(u+4)*32 + lane]; }
        }
    }
}

// copy helper: 16 rows x 2KB from global bf16 into padded smem via cp.async
static __device__ __forceinline__ void copy_tile(__nv_bfloat16* dstBase,
                                                 const __nv_bfloat16* __restrict__ src,
                                                 int tid) {
#pragma unroll
    for (int s = 0; s < 8; s++) {
        int e = tid + s * NTHREADS;
        int row = e >> 7, seg = e & 127;
        unsigned dst = smem_u32(dstBase + row * PADC + seg * 8);
        asm volatile("cp.async.cg.shared.global [%0], [%1], 16;\n"
                     :: "r"(dst), "l"((const void*)(src + row * SW + seg * 8)));
    }
    asm volatile("cp.async.commit_group;\n" ::: "memory");
}

// ---------------- setup 0: inv, u0, counters ----------------
__global__ void setup0(const float* __restrict__ x, const float* __restrict__ init,
                       const int* __restrict__ rp) {
    int tid = blockIdx.x * blockDim.x + threadIdx.x;
    if (tid < 2 * 8 * 64) d_cnt[tid] = 0u;
    if (tid < SW) d_inv[rp[tid]] = tid;
    const float eps = EPS_F;
    for (int e = tid; e < BATCH * SW; e += gridDim.x * blockDim.x) {
        int b = e >> 10, p = e & (SW - 1);
        float v = eps * init[p];
        if (p < IN_W) v += x[b * IN_W + p];
        d_Uf[0][b * SW + p] = v;
        d_Uh[0][b * SW + p] = __float2bfloat16(v);
    }
}

// ---------------- fused setup: M (blocks 0-1023), h0 (1024-1087), c2 (1088-1215) ----
__global__ void setup_rest(const float* __restrict__ W1, const float* __restrict__ b1,
                           const float* __restrict__ W2, const float* __restrict__ b2,
                           const int* __restrict__ rp) {
    __shared__ float As[32][33], Bs[32][33];
    const int bid = blockIdx.x;
    const int tx = threadIdx.x & 15, ty = threadIdx.x >> 4;
    const int lin = threadIdx.x;

    if (bid < 1024) {
        int jb = (bid >> 5) * 32, mb = (bid & 31) * 32;
        float acc00 = 0.f, acc01 = 0.f, acc10 = 0.f, acc11 = 0.f;
        for (int kc = 0; kc < 32; kc++) {
#pragma unroll
            for (int i = 0; i < 4; i++) {
                int e = lin + i * 256;
                int r = e >> 5, c = e & 31;
                As[r][c] = W1[(size_t)(jb + r) * SW + kc * 32 + c];
                Bs[r][c] = W2[(size_t)rp[kc * 32 + r] * SW + mb + c];
            }
            __syncthreads();
#pragma unroll
            for (int kk = 0; kk < 32; kk++) {
                float a0 = As[ty * 2][kk], a1 = As[ty * 2 + 1][kk];
                float b0 = Bs[kk][tx * 2], b1 = Bs[kk][tx * 2 + 1];
                acc00 += a0 * b0; acc01 += a0 * b1;
                acc10 += a1 * b0; acc11 += a1 * b1;
            }
            __syncthreads();
        }
        d_M[(size_t)(jb + ty * 2)     * SW + mb + tx * 2]     = acc00;
        d_M[(size_t)(jb + ty * 2)     * SW + mb + tx * 2 + 1] = acc01;
        d_M[(size_t)(jb + ty * 2 + 1) * SW + mb + tx * 2]     = acc10;
        d_M[(size_t)(jb + ty * 2 + 1) * SW + mb + tx * 2 + 1] = acc11;
    } else if (bid < 1088) {
        int lb = bid - 1024;
        int bb = (lb >> 5) * 32, jb = (lb & 31) * 32;
        float acc00 = 0.f, acc01 = 0.f, acc10 = 0.f, acc11 = 0.f;
        for (int kc = 0; kc < 32; kc++) {
#pragma unroll
            for (int i = 0; i < 4; i++) {
                int e = lin + i * 256;
                int r = e >> 5, c = e & 31;
                As[r][c] = d_Uf[0][(size_t)(bb + r) * SW + rp[kc * 32 + c]];
                Bs[r][c] = W1[(size_t)(jb + r) * SW + kc * 32 + c];
            }
            __syncthreads();
#pragma unroll
            for (int kk = 0; kk < 32; kk++) {
                float a0 = As[ty * 2][kk], a1 = As[ty * 2 + 1][kk];
                float b0 = Bs[tx * 2][kk], b1 = Bs[tx * 2 + 1][kk];
                acc00 += a0 * b0; acc01 += a0 * b1;
                acc10 += a1 * b0; acc11 += a1 * b1;
            }
            __syncthreads();
        }
        int j0 = jb + tx * 2, j1 = j0 + 1;
        d_Hh[0][(size_t)(bb + ty*2)     * SW + j0] = __float2bfloat16(fmaxf(acc00 + b1[j0], 0.f));
        d_Hh[0][(size_t)(bb + ty*2)     * SW + j1] = __float2bfloat16(fmaxf(acc01 + b1[j1], 0.f));
        d_Hh[0][(size_t)(bb + ty*2 + 1) * SW + j0] = __float2bfloat16(fmaxf(acc10 + b1[j0], 0.f));
        d_Hh[0][(size_t)(bb + ty*2 + 1) * SW + j1] = __float2bfloat16(fmaxf(acc11 + b1[j1], 0.f));
    } else {
        float* pb2 = &As[0][0];
        for (int k = lin; k < SW; k += 256) pb2[k] = b2[rp[k]];
        __syncthreads();
        int warp = lin >> 5, lane = lin & 31;
        int j = (bid - 1088) * 8 + warp;
        float acc = 0.f;
        for (int i = lane; i < SW; i += 32) acc += W1[(size_t)j * SW + i] * pb2[i];
#pragma unroll
        for (int o = 16; o > 0; o >>= 1) acc += __shfl_down_sync(0xffffffff, acc, o);
        if (lane == 0) d_c2[j] = acc;
    }
}

// ---------------- persistent one-barrier-per-step RNN kernel ----------------
__global__ void __launch_bounds__(NTHREADS)
resrnn_kernel(const float* __restrict__ x, const int* __restrict__ rp,
              const float* __restrict__ W1, const float* __restrict__ b1,
              const float* __restrict__ W2, const float* __restrict__ b2,
              float* __restrict__ out, int out_size) {
    extern __shared__ char smem[];
    __nv_bfloat16* W1pps = (__nv_bfloat16*)(smem + W1PP_OFF);  // [16][PADC]
    __nv_bfloat16* Ms    = (__nv_bfloat16*)(smem + M_OFF);     // [16][PADC]
    __nv_bfloat16* W2s   = (__nv_bfloat16*)(smem + W2_OFF);    // [16][PADC]
    __nv_bfloat16* Xws   = (__nv_bfloat16*)(smem + XW_OFF);    // [16][PADX]
    __nv_bfloat16* Act0  = (__nv_bfloat16*)(smem + ACT0_OFF);  // [16][PADC] (u subtile)
    __nv_bfloat16* Act1  = (__nv_bfloat16*)(smem + ACT1_OFF);  // [16][PADC] (h subtile)
    char*          XactB = smem + XACT_OFF;                     // [32][PADX] bf16
    float*         Red   = (float*)(smem + RED_OFF);            // [6][256]

    const int tid   = threadIdx.x;
    const int cta   = blockIdx.x;
    const int cg    = cta & 63;
    const int bh    = cta >> 6;                 // row half = barrier domain
    const int jbase = cg * JS;
    const int rbase = bh * RWS;
    const float eps = EPS_F;
    const float inv_eps = 1.0f / eps;

    // ---- stage inv and inv2 (reuse Act regions), then load weight slices ----
    {
        int* invs  = (int*)Act0;
        int* inv2s = (int*)Act1;
        for (int e = tid; e < SW; e += NTHREADS) invs[e] = d_inv[e];
        __syncthreads();
        for (int e = tid; e < SW; e += NTHREADS) inv2s[e] = invs[invs[e]];
        __syncthreads();
        for (int e = tid; e < JS * SW; e += NTHREADS) {
            int n = e >> 10, q = e & (SW - 1);
            W1pps[n * PADC + q] = __float2bfloat16(W1[(size_t)(jbase + n) * SW + inv2s[q]]);
            Ms[n * PADC + q]    = __float2bfloat16(d_M[(size_t)(jbase + n) * SW + q]);
            W2s[n * PADC + q]   = __float2bfloat16(W2[(size_t)(jbase + n) * SW + q]);
        }
        for (int e = tid; e < JS * IN_W; e += NTHREADS) {
            int n = e >> 8, i = e & (IN_W - 1);
            Xws[n * PADX + i] = __float2bfloat16(W1[(size_t)(jbase + n) * SW + invs[i]] * inv_eps);
        }
        __syncthreads();
    }

    // ---- per-thread static coordinates ----
    const int warp = tid >> 5, lane = tid & 31;
    const int nhalf = warp & 1;
    const int kq    = warp >> 1;
    const int g  = lane >> 2, tc = (lane & 3) * 2;

    // A-operand ldsm offset (16 rows x one k16 step per ldsm4)
    const unsigned aOffC = (unsigned)((lane & 15) * (PADC * 2) + ((lane >> 4) << 4) + kq * 512);
    const unsigned aOffX = (unsigned)((lane & 15) * (PADX * 2) + ((lane >> 4) << 4) + kq * 128);
    // B-operand ldsm offset: this warp's 8 rows, 4 fragments span 2 k-steps (64B)
    const unsigned bOffC = (unsigned)((nhalf * 8 + (lane & 7)) * (PADC * 2) + ((lane >> 3) << 4) + kq * 512);
    const unsigned bOffX = (unsigned)((nhalf * 8 + (lane & 7)) * (PADX * 2) + ((lane >> 3) << 4) + kq * 128);

    const unsigned aU  = smem_u32(Act0) + aOffC;
    const unsigned aH  = smem_u32(Act1) + aOffC;
    const unsigned bW1 = smem_u32(W1pps) + bOffC;
    const unsigned bM  = smem_u32(Ms) + bOffC;
    const unsigned bW2 = smem_u32(W2s) + bOffC;
    const unsigned bX  = smem_u32(Xws) + bOffX;
    const unsigned aX0 = smem_u32(XactB) + aOffX;
    const unsigned aX1 = aX0 + (unsigned)(STR * PADX * 2);

    const int j0 = jbase + nhalf * 8 + tc, j1 = j0 + 1;
    const float bb2_0 = b2[j0], bb2_1 = b2[j1];
    const float cf0 = b1[j0] + eps * d_c2[j0];
    const float cf1 = b1[j1] + eps * d_c2[j1];
    const int rp0 = rp[j0], rp1 = rp[j1];
    const bool epi = (kq == 0);
    const bool has_x = (jbase < IN_W);
    const int gA0 = rbase + g, gA1 = rbase + g + 8;          // subtile 0
    const int gB0 = gA0 + STR, gB1 = gA1 + STR;              // subtile 1

    float sp[8], xe[8];

    for (int t = 0; t < SEQ; t++) {
        const int cur = t & 1, nxt = cur ^ 1;
        const bool last = (t == SEQ - 1);
        const __nv_bfloat16* Ug = d_Uh[cur] + (size_t)rbase * SW;
        const __nv_bfloat16* Hg = d_Hh[cur] + (size_t)rbase * SW;

        // ---- prefetch epilogue operands ----
        if (epi) {
            const float* Uc = d_Uf[cur];
            sp[0] = ldcg_f(Uc + gA0 * SW + rp0);
            sp[1] = ldcg_f(Uc + gA0 * SW + rp1);
            sp[2] = ldcg_f(Uc + gA1 * SW + rp0);
            sp[3] = ldcg_f(Uc + gA1 * SW + rp1);
            sp[4] = ldcg_f(Uc + gB0 * SW + rp0);
            sp[5] = ldcg_f(Uc + gB0 * SW + rp1);
            sp[6] = ldcg_f(Uc + gB1 * SW + rp0);
            sp[7] = ldcg_f(Uc + gB1 * SW + rp1);
            if (has_x && !last) {
                const float* xb = x + (size_t)(t + 1) * BATCH * IN_W;
                ld2cg(xe[0], xe[1], xb + gA0 * IN_W + j0);
                ld2cg(xe[2], xe[3], xb + gA1 * IN_W + j0);
                ld2cg(xe[4], xe[5], xb + gB0 * IN_W + j0);
                ld2cg(xe[6], xe[7], xb + gB1 * IN_W + j0);
            }
        }

        // ---- stage x_{t+1} (all 32 rows) fp32->bf16 into Xact ----
        if (!last) {
            const float4* xs = (const float4*)(x + (size_t)(t + 1) * BATCH * IN_W
                                               + (size_t)rbase * IN_W);
#pragma unroll
            for (int i = 0; i < 8; i++) {
                int e = tid + i * NTHREADS;      // 0..2047 = 32 rows x 64 float4
                int row = e >> 6, seg = e & 63;
                float4 v = __ldg(xs + row * 64 + seg);
                __nv_bfloat162 p0 = __floats2bfloat162_rn(v.x, v.y);
                __nv_bfloat162 p1 = __floats2bfloat162_rn(v.z, v.w);
                uint32_t* dst = (uint32_t*)(XactB + row * (PADX * 2) + seg * 8);
                dst[0] = *(uint32_t*)&p0;
                dst[1] = *(uint32_t*)&p1;
            }
        }

        // ---- issue subtile-0 copies ----
        copy_tile(Act0, Ug, tid);                  // group: U0
        copy_tile(Act1, Hg, tid);                  // group: H0

        float z1[4] = {0,0,0,0}, zy[4] = {0,0,0,0}, yy[4] = {0,0,0,0};
        asm volatile("cp.async.wait_group 1;\n" ::: "memory");   // U0 done
        __syncthreads();                          // u subtile 0 visible (and Xact staged)
        gemmK1024(aU, bW1, z1);
        __syncthreads();                          // all warps done reading Act0

        // ---- issue U1 copy into Act0 (drains under gemmH0x2) ----
        copy_tile(Act0, Ug + STR * SW, tid);       // group: U1

        asm volatile("cp.async.wait_group 1;\n" ::: "memory");   // H0 done (U1 pending)
        __syncthreads();                          // h subtile 0 visible
        gemmK1024x2(aH, bM, bW2, zy, yy);
        if (!last) gemmK256(aX0, bX, zy);
        __syncthreads();                          // all warps done reading Act1

        // ---- issue H1 copy into Act1 (drains under reduce/epilogue) ----
        copy_tile(Act1, Hg + STR * SW, tid);       // group: H1

        // ---- subtile 0: combine, reduce, epilogue ----
        float zc[4];
#pragma unroll
        for (int u = 0; u < 4; u++) zc[u] = LIN_F * z1[u] + eps * zy[u];
        kreduce8(Red, nhalf, kq, lane, zc, yy);
        if (epi) {
            float nv0 = LIN_F * sp[0] + eps * (yy[0] + bb2_0);
            float nv1 = LIN_F * sp[1] + eps * (yy[1] + bb2_1);
            float nv2 = LIN_F * sp[2] + eps * (yy[2] + bb2_0);
            float nv3 = LIN_F * sp[3] + eps * (yy[3] + bb2_1);
            if (!last) {
                if (has_x) { nv0 += xe[0]; nv1 += xe[1]; nv2 += xe[2]; nv3 += xe[3]; }
                float* Un = d_Uf[nxt];
                __nv_bfloat162* Uhn = (__nv_bfloat162*)d_Uh[nxt];
                __nv_bfloat162* Hhn = (__nv_bfloat162*)d_Hh[nxt];
                st2cg(Un + gA0 * SW + j0, nv0, nv1);
                st2cg(Un + gA1 * SW + j0, nv2, nv3);
                Uhn[(gA0 * SW + j0) >> 1] = __floats2bfloat162_rn(nv0, nv1);
                Uhn[(gA1 * SW + j0) >> 1] = __floats2bfloat162_rn(nv2, nv3);
                float h0 = fmaxf(zc[0] + cf0, 0.f), h1 = fmaxf(zc[1] + cf1, 0.f);
                float h2 = fmaxf(zc[2] + cf0, 0.f), h3 = fmaxf(zc[3] + cf1, 0.f);
                Hhn[(gA0 * SW + j0) >> 1] = __floats2bfloat162_rn(h0, h1);
                Hhn[(gA1 * SW + j0) >> 1] = __floats2bfloat162_rn(h2, h3);
            } else {
                const int rr[4] = { gA0, gA0, gA1, gA1 };
                const int jj[4] = { j0, j1, j0, j1 };
                const float vv[4] = { nv0, nv1, nv2, nv3 };
#pragma unroll
                for (int u = 0; u < 4; u++) {
                    int b = rr[u], i = jj[u]; float v = vv[u];
                    if (out_size == BATCH * (OUT_W + SW)) {
                        out[BATCH * OUT_W + b * SW + i] = v;
                        if (i >= SW - OUT_W) out[b * OUT_W + (i - (SW - OUT_W))] = v;
                    } else if (out_size == BATCH * SW) {
                        out[b * SW + i] = v;
                    } else {
                        if (i >= SW - OUT_W) out[b * OUT_W + (i - (SW - OUT_W))] = v;
                    }
                }
            }
        }

        // ---- subtile 1: GEMMs ----
#pragma unroll
        for (int u = 0; u < 4; u++) { z1[u] = 0.f; zy[u] = 0.f; yy[u] = 0.f; }
        asm volatile("cp.async.wait_group 1;\n" ::: "memory");   // U1 done (H1 pending)
        __syncthreads();
        gemmK1024(aU, bW1, z1);
        asm volatile("cp.async.wait_group 0;\n" ::: "memory");   // H1 done
        __syncthreads();
        gemmK1024x2(aH, bM, bW2, zy, yy);
        if (!last) gemmK256(aX1, bX, zy);
#pragma unroll
        for (int u = 0; u < 4; u++) zc[u] = LIN_F * z1[u] + eps * zy[u];
        kreduce8(Red, nhalf, kq, lane, zc, yy);
        if (epi) {
            float nv0 = LIN_F * sp[4] + eps * (yy[0] + bb2_0);
            float nv1 = LIN_F * sp[5] + eps * (yy[1] + bb2_1);
            float nv2 = LIN_F * sp[6] + eps * (yy[2] + bb2_0);
            float nv3 = LIN_F * sp[7] + eps * (yy[3] + bb2_1);
            if (!last) {
                if (has_x) { nv0 += xe[4]; nv1 += xe[5]; nv2 += xe[6]; nv3 += xe[7]; }
                float* Un = d_Uf[nxt];
                __nv_bfloat162* Uhn = (__nv_bfloat162*)d_Uh[nxt];
                __nv_bfloat162* Hhn = (__nv_bfloat162*)d_Hh[nxt];
                st2cg(Un + gB0 * SW + j0, nv0, nv1);
                st2cg(Un + gB1 * SW + j0, nv2, nv3);
                Uhn[(gB0 * SW + j0) >> 1] = __floats2bfloat162_rn(nv0, nv1);
                Uhn[(gB1 * SW + j0) >> 1] = __floats2bfloat162_rn(nv2, nv3);
                float h0 = fmaxf(zc[0] + cf0, 0.f), h1 = fmaxf(zc[1] + cf1, 0.f);
                float h2 = fmaxf(zc[2] + cf0, 0.f), h3 = fmaxf(zc[3] + cf1, 0.f);
                Hhn[(gB0 * SW + j0) >> 1] = __floats2bfloat162_rn(h0, h1);
                Hhn[(gB1 * SW + j0) >> 1] = __floats2bfloat162_rn(h2, h3);
            } else {
                const int rr[4] = { gB0, gB0, gB1, gB1 };
                const int jj[4] = { j0, j1, j0, j1 };
                const float vv[4] = { nv0, nv1, nv2, nv3 };
#pragma unroll
                for (int u = 0; u < 4; u++) {
                    int b = rr[u], i = jj[u]; float v = vv[u];
                    if (out_size == BATCH * (OUT_W + SW)) {
                        out[BATCH * OUT_W + b * SW + i] = v;
                        if (i >= SW - OUT_W) out[b * OUT_W + (i - (SW - OUT_W))] = v;
                    } else if (out_size == BATCH * SW) {
                        out[b * SW + i] = v;
                    } else {
                        if (i >= SW - OUT_W) out[b * OUT_W + (i - (SW - OUT_W))] = v;
                    }
                }
            }
        }

        // ---- single barrier per step ----
        if (!last) {
            bar_arrive(bh, cg);
            bar_wait(bh, (unsigned)(t + 1) * DOM_CTAS);
        }
    }
}

// ---------------- launch ----------------
extern "C" void kernel_launch(void* const* d_in, const int* in_sizes, int n_in,
                              void* d_out, int out_size) {
    const float* x    = (const float*)d_in[0];
    const float* init = (const float*)d_in[1];
    const int*   rp   = (const int*)  d_in[2];
    const float* W1   = (const float*)d_in[3];
    const float* b1   = (const float*)d_in[4];
    const float* W2   = (const float*)d_in[5];
    const float* b2   = (const float*)d_in[6];

    setup0<<<64, 256>>>(x, init, rp);
    setup_rest<<<1216, 256>>>(W1, b1, W2, b2, rp);

    cudaFuncSetAttribute(resrnn_kernel, cudaFuncAttributeMaxDynamicSharedMemorySize, SMEM_TOTAL);
    resrnn_kernel<<<P_CTAS, NTHREADS, SMEM_TOTAL>>>(x, rp, W1, b1, W2, b2,
                                                    (float*)d_out, out_size);
}